// round 3
// baseline (speedup 1.0000x reference)
#include <cuda_runtime.h>
#include <math.h>

// Problem constants
#define PB 8
#define PN 1025
#define PD 1024
#define PH 16
#define PDh 64
#define PM (PB*PN)      // 8200 rows
#define PEPS 1e-8f

// Scratch (device globals: allocation-free rule)
__device__ float g_h  [(size_t)PM * PD];        // rmsnorm output
__device__ float g_qkv[(size_t)PM * 3 * PD];    // qkv projections (rope applied in place)
__device__ float g_y  [(size_t)PM * PD];        // attention output, [B,N,H*Dh]
__device__ float g_t1 [(size_t)PM * PD];        // y @ out_w^T + out_b

// ---------------------------------------------------------------------------
// Block reduction helper (256 threads)
// ---------------------------------------------------------------------------
__device__ __forceinline__ float blockReduceSum256(float v, float* sbuf) {
    __syncthreads();
    int lane = threadIdx.x & 31, wid = threadIdx.x >> 5;
    #pragma unroll
    for (int o = 16; o > 0; o >>= 1) v += __shfl_xor_sync(0xffffffffu, v, o);
    if (lane == 0) sbuf[wid] = v;
    __syncthreads();
    float r = 0.f;
    #pragma unroll
    for (int w = 0; w < 8; w++) r += sbuf[w];
    return r;
}

// ---------------------------------------------------------------------------
// Kernel 1: zero-centered RMSNorm, one block per row (D=1024, 256 thr x 4)
// ---------------------------------------------------------------------------
__global__ __launch_bounds__(256) void rmsnorm_kernel(
    const float* __restrict__ x, const float* __restrict__ g,
    float* __restrict__ h)
{
    __shared__ float sbuf[8];
    int row = blockIdx.x;
    const float* xr = x + (size_t)row * PD;
    int t = threadIdx.x;
    float v[4];
    float s = 0.f;
    #pragma unroll
    for (int i = 0; i < 4; i++) { v[i] = xr[i * 256 + t]; s += v[i]; }
    s = blockReduceSum256(s, sbuf);
    float mean = s * (1.f / (float)PD);
    float s2 = 0.f;
    #pragma unroll
    for (int i = 0; i < 4; i++) { float c = v[i] - mean; s2 += c * c; }
    s2 = blockReduceSum256(s2, sbuf);
    float scale = rsqrtf(s2 * (1.f / (float)PD) + PEPS);
    float* hr = h + (size_t)row * PD;
    #pragma unroll
    for (int i = 0; i < 4; i++)
        hr[i * 256 + t] = (v[i] - mean) * scale * g[i * 256 + t];
}

// ---------------------------------------------------------------------------
// Kernel 2: SGEMM  C[M,Nc] = A[M,K] * W[Nc,K]^T (+bias / +final epilogue)
// 128x128 block tile, BK=8, 256 threads, 8x8 per thread, reg prefetch.
// EPI=0: C = acc + bias
// EPI=1: C = xres + sigmoid(acc + bias) * t1    (final gated residual)
// ---------------------------------------------------------------------------
template<int EPI>
__global__ __launch_bounds__(256) void sgemm_nt(
    const float* __restrict__ A, const float* __restrict__ W,
    const float* __restrict__ bias, float* __restrict__ C,
    int M, int Nc, int K,
    const float* __restrict__ xres, const float* __restrict__ t1)
{
    __shared__ float As[8][128];
    __shared__ float Bs[8][128];

    int tid = threadIdx.x;
    int m0 = blockIdx.y * 128, n0 = blockIdx.x * 128;
    int tx = tid & 15, ty = tid >> 4;
    int lr = tid >> 1;          // 0..127
    int lk = (tid & 1) * 4;     // 0 or 4

    float acc[8][8];
    #pragma unroll
    for (int i = 0; i < 8; i++)
        #pragma unroll
        for (int j = 0; j < 8; j++) acc[i][j] = 0.f;

    bool avalid = (m0 + lr) < M;
    const float* Aptr = A + (size_t)(m0 + lr) * K + lk;
    const float* Wptr = W + (size_t)(n0 + lr) * K + lk;

    float4 a = avalid ? *(const float4*)(Aptr) : make_float4(0.f,0.f,0.f,0.f);
    float4 w = *(const float4*)(Wptr);

    for (int k0 = 0; k0 < K; k0 += 8) {
        As[lk + 0][lr] = a.x; As[lk + 1][lr] = a.y;
        As[lk + 2][lr] = a.z; As[lk + 3][lr] = a.w;
        Bs[lk + 0][lr] = w.x; Bs[lk + 1][lr] = w.y;
        Bs[lk + 2][lr] = w.z; Bs[lk + 3][lr] = w.w;
        __syncthreads();

        float4 an = make_float4(0.f,0.f,0.f,0.f), wn = an;
        if (k0 + 8 < K) {
            if (avalid) an = *(const float4*)(Aptr + k0 + 8);
            wn = *(const float4*)(Wptr + k0 + 8);
        }

        #pragma unroll
        for (int kk = 0; kk < 8; kk++) {
            float4 ra0 = *(const float4*)&As[kk][ty * 8];
            float4 ra1 = *(const float4*)&As[kk][ty * 8 + 4];
            float4 rb0 = *(const float4*)&Bs[kk][tx * 8];
            float4 rb1 = *(const float4*)&Bs[kk][tx * 8 + 4];
            float ra[8] = {ra0.x, ra0.y, ra0.z, ra0.w, ra1.x, ra1.y, ra1.z, ra1.w};
            float rb[8] = {rb0.x, rb0.y, rb0.z, rb0.w, rb1.x, rb1.y, rb1.z, rb1.w};
            #pragma unroll
            for (int i = 0; i < 8; i++)
                #pragma unroll
                for (int j = 0; j < 8; j++)
                    acc[i][j] += ra[i] * rb[j];
        }
        __syncthreads();
        a = an; w = wn;
    }

    #pragma unroll
    for (int i = 0; i < 8; i++) {
        int gr = m0 + ty * 8 + i;
        if (gr >= M) continue;
        size_t rowoff = (size_t)gr * Nc;
        #pragma unroll
        for (int j = 0; j < 8; j++) {
            int gc = n0 + tx * 8 + j;
            float v = acc[i][j] + bias[gc];
            if (EPI == 0) {
                C[rowoff + gc] = v;
            } else {
                float gate = 1.f / (1.f + __expf(-v));
                C[rowoff + gc] = xres[rowoff + gc] + gate * t1[rowoff + gc];
            }
        }
    }
}

// ---------------------------------------------------------------------------
// Kernel 3: RoPE applied in place to q,k portions of qkv
// one thread per (row, head, d2) handles both q and k pair
// ---------------------------------------------------------------------------
__global__ __launch_bounds__(256) void rope_kernel(
    float* __restrict__ qkv, const float* __restrict__ fc)
{
    int idx = blockIdx.x * blockDim.x + threadIdx.x;
    const int total = PM * PH * (PDh / 2);   // 8200*16*32
    if (idx >= total) return;
    int d2  = idx & 31;
    int h   = (idx >> 5) & 15;
    int row = idx >> 9;
    int n   = row % PN;
    float fr = fc[(n * 32 + d2) * 2 + 0];
    float fi = fc[(n * 32 + d2) * 2 + 1];
    size_t base = (size_t)row * 3072 + h * 64 + d2 * 2;
    float2 q = *(float2*)(qkv + base);
    *(float2*)(qkv + base) = make_float2(q.x * fr - q.y * fi, q.x * fi + q.y * fr);
    float2 k = *(float2*)(qkv + base + 1024);
    *(float2*)(qkv + base + 1024) = make_float2(k.x * fr - k.y * fi, k.x * fi + k.y * fr);
}

// ---------------------------------------------------------------------------
// Kernel 4: flash attention with additive bias.
// Block = 256 thr, handles (b, h, 64-query tile). 64-key tiles, online softmax.
// smem (dynamic, 67328 B): Qs/Ks/Vs/Ss [64][65] + m/l/corr[64]
// ---------------------------------------------------------------------------
__global__ __launch_bounds__(256) void flash_kernel(
    const float* __restrict__ qkv, const float* __restrict__ Bbias,
    float* __restrict__ y)
{
    extern __shared__ float sm[];
    float* Qs  = sm;
    float* Ks  = sm + 4160;          // 64*65
    float* Vs  = sm + 2 * 4160;
    float* Ss  = sm + 3 * 4160;
    float* m_s = sm + 4 * 4160;
    float* l_s = m_s + 64;
    float* c_s = l_s + 64;

    int b = blockIdx.z, h = blockIdx.y, q0 = blockIdx.x * 64;
    int tid = threadIdx.x, tx = tid & 15, ty = tid >> 4;

    // load Q tile, pre-scaled by 1/sqrt(Dh)
    for (int idx = tid; idx < 64 * 64; idx += 256) {
        int r = idx >> 6, d = idx & 63;
        int qr = q0 + r;
        Qs[r * 65 + d] = (qr < PN)
            ? qkv[((size_t)(b * PN + qr)) * 3072 + h * 64 + d] * 0.125f : 0.f;
    }
    if (tid < 64) { m_s[tid] = -1e30f; l_s[tid] = 0.f; }
    float acc[4][4] = {};
    __syncthreads();

    for (int k0 = 0; k0 < PN; k0 += 64) {
        // load K,V tiles
        for (int idx = tid; idx < 64 * 64; idx += 256) {
            int r = idx >> 6, d = idx & 63;
            int kr = k0 + r;
            if (kr < PN) {
                size_t base = ((size_t)(b * PN + kr)) * 3072 + h * 64 + d;
                Ks[r * 65 + d] = qkv[base + 1024];
                Vs[r * 65 + d] = qkv[base + 2048];
            } else {
                Ks[r * 65 + d] = 0.f; Vs[r * 65 + d] = 0.f;
            }
        }
        __syncthreads();

        // S = Q K^T (scale already folded into Q)
        float s[4][4] = {};
        #pragma unroll 4
        for (int d = 0; d < 64; d++) {
            float ra[4], rb[4];
            #pragma unroll
            for (int i = 0; i < 4; i++) ra[i] = Qs[(ty * 4 + i) * 65 + d];
            #pragma unroll
            for (int j = 0; j < 4; j++) rb[j] = Ks[(tx * 4 + j) * 65 + d];
            #pragma unroll
            for (int i = 0; i < 4; i++)
                #pragma unroll
                for (int j = 0; j < 4; j++) s[i][j] += ra[i] * rb[j];
        }

        // bias + mask -> Ss
        #pragma unroll
        for (int i = 0; i < 4; i++) {
            int gr = q0 + ty * 4 + i;
            #pragma unroll
            for (int j = 0; j < 4; j++) {
                int gc = k0 + tx * 4 + j;
                float v;
                if (gc < PN) {
                    v = s[i][j];
                    if (gr < PN) v += Bbias[(size_t)gr * PN + gc];
                } else v = -1e30f;
                Ss[(ty * 4 + i) * 65 + tx * 4 + j] = v;
            }
        }
        __syncthreads();

        // online softmax: 4 threads per row
        {
            int row = tid >> 2, seg = tid & 3;
            float mx = -1e30f;
            #pragma unroll
            for (int e = 0; e < 16; e++)
                mx = fmaxf(mx, Ss[row * 65 + seg * 16 + e]);
            mx = fmaxf(mx, __shfl_xor_sync(0xffffffffu, mx, 1));
            mx = fmaxf(mx, __shfl_xor_sync(0xffffffffu, mx, 2));
            float m_old = m_s[row];
            float m_new = fmaxf(m_old, mx);
            float sum = 0.f;
            #pragma unroll
            for (int e = 0; e < 16; e++) {
                float p = __expf(Ss[row * 65 + seg * 16 + e] - m_new);
                Ss[row * 65 + seg * 16 + e] = p;
                sum += p;
            }
            sum += __shfl_xor_sync(0xffffffffu, sum, 1);
            sum += __shfl_xor_sync(0xffffffffu, sum, 2);
            if (seg == 0) {
                float corr = __expf(m_old - m_new);
                c_s[row] = corr;
                l_s[row] = l_s[row] * corr + sum;
                m_s[row] = m_new;
            }
        }
        __syncthreads();

        // rescale O and accumulate P @ V
        float cr[4];
        #pragma unroll
        for (int i = 0; i < 4; i++) cr[i] = c_s[ty * 4 + i];
        #pragma unroll
        for (int i = 0; i < 4; i++)
            #pragma unroll
            for (int j = 0; j < 4; j++) acc[i][j] *= cr[i];
        #pragma unroll 4
        for (int kk = 0; kk < 64; kk++) {
            float rp[4], rv[4];
            #pragma unroll
            for (int i = 0; i < 4; i++) rp[i] = Ss[(ty * 4 + i) * 65 + kk];
            #pragma unroll
            for (int j = 0; j < 4; j++) rv[j] = Vs[kk * 65 + tx * 4 + j];
            #pragma unroll
            for (int i = 0; i < 4; i++)
                #pragma unroll
                for (int j = 0; j < 4; j++) acc[i][j] += rp[i] * rv[j];
        }
        __syncthreads();
    }

    // normalize and write y[b, q, h*64 + d]
    #pragma unroll
    for (int i = 0; i < 4; i++) {
        int gr = q0 + ty * 4 + i;
        if (gr >= PN) continue;
        float inv = 1.f / l_s[ty * 4 + i];
        #pragma unroll
        for (int j = 0; j < 4; j++)
            y[((size_t)(b * PN + gr)) * PD + h * 64 + tx * 4 + j] = acc[i][j] * inv;
    }
}

// ---------------------------------------------------------------------------
// Launch
// ---------------------------------------------------------------------------
extern "C" void kernel_launch(void* const* d_in, const int* in_sizes, int n_in,
                              void* d_out, int out_size)
{
    (void)in_sizes; (void)n_in; (void)out_size;
    const float* x      = (const float*)d_in[0];
    const float* fc     = (const float*)d_in[1];
    const float* g      = (const float*)d_in[2];
    const float* qkv_w  = (const float*)d_in[3];
    const float* qkv_b  = (const float*)d_in[4];
    const float* out_w  = (const float*)d_in[5];
    const float* out_b  = (const float*)d_in[6];
    const float* gate_w = (const float*)d_in[7];
    const float* gate_b = (const float*)d_in[8];
    const float* Bbias  = (const float*)d_in[9];
    float* out = (float*)d_out;

    float *h, *qkv, *y, *t1;
    cudaGetSymbolAddress((void**)&h,   g_h);
    cudaGetSymbolAddress((void**)&qkv, g_qkv);
    cudaGetSymbolAddress((void**)&y,   g_y);
    cudaGetSymbolAddress((void**)&t1,  g_t1);

    // 1. zero-centered RMSNorm
    rmsnorm_kernel<<<PM, 256>>>(x, g, h);

    // 2. QKV projection: [8200,1024] @ [3072,1024]^T
    dim3 g1(3072 / 128, (PM + 127) / 128);
    sgemm_nt<0><<<g1, 256>>>(h, qkv_w, qkv_b, qkv, PM, 3072, PD, nullptr, nullptr);

    // 3. RoPE on q,k
    int nrope = PM * PH * (PDh / 2);
    rope_kernel<<<(nrope + 255) / 256, 256>>>(qkv, fc);

    // 4. flash attention
    cudaFuncSetAttribute(flash_kernel,
                         cudaFuncAttributeMaxDynamicSharedMemorySize, 67328);
    flash_kernel<<<dim3((PN + 63) / 64, PH, PB), 256, 67328>>>(qkv, Bbias, y);

    // 5. out projection: t1 = y @ out_w^T + out_b
    dim3 g2(PD / 128, (PM + 127) / 128);
    sgemm_nt<0><<<g2, 256>>>(y, out_w, out_b, t1, PM, PD, PD, nullptr, nullptr);

    // 6. gated residual: out = x + sigmoid(h @ gate_w^T + gate_b) * t1
    sgemm_nt<1><<<g2, 256>>>(h, gate_w, gate_b, out, PM, PD, PD, x, t1);
}

// round 4
// speedup vs baseline: 1.5323x; 1.5323x over previous
#include <cuda_runtime.h>
#include <math.h>

// Problem constants
#define PB 8
#define PN 1025
#define PD 1024
#define PH 16
#define PDh 64
#define PM (PB*PN)      // 8200 rows
#define PEPS 1e-8f

// Scratch (device globals: allocation-free rule)
__device__ float g_h  [(size_t)PM * PD];
__device__ float g_qkv[(size_t)PM * 3 * PD];
__device__ float g_y  [(size_t)PM * PD];
__device__ float g_t1 [(size_t)PM * PD];

__device__ __forceinline__ float to_tf32(float x) {
    float r;
    asm("cvt.rna.tf32.f32 %0, %1;" : "=f"(r) : "f"(x));
    return r;
}

// ---------------------------------------------------------------------------
// Block reduction helper (256 threads)
// ---------------------------------------------------------------------------
__device__ __forceinline__ float blockReduceSum256(float v, float* sbuf) {
    __syncthreads();
    int lane = threadIdx.x & 31, wid = threadIdx.x >> 5;
    #pragma unroll
    for (int o = 16; o > 0; o >>= 1) v += __shfl_xor_sync(0xffffffffu, v, o);
    if (lane == 0) sbuf[wid] = v;
    __syncthreads();
    float r = 0.f;
    #pragma unroll
    for (int w = 0; w < 8; w++) r += sbuf[w];
    return r;
}

// ---------------------------------------------------------------------------
// Kernel 1: zero-centered RMSNorm
// ---------------------------------------------------------------------------
__global__ __launch_bounds__(256) void rmsnorm_kernel(
    const float* __restrict__ x, const float* __restrict__ g,
    float* __restrict__ h)
{
    __shared__ float sbuf[8];
    int row = blockIdx.x;
    const float* xr = x + (size_t)row * PD;
    int t = threadIdx.x;
    float v[4];
    float s = 0.f;
    #pragma unroll
    for (int i = 0; i < 4; i++) { v[i] = xr[i * 256 + t]; s += v[i]; }
    s = blockReduceSum256(s, sbuf);
    float mean = s * (1.f / (float)PD);
    float s2 = 0.f;
    #pragma unroll
    for (int i = 0; i < 4; i++) { float c = v[i] - mean; s2 += c * c; }
    s2 = blockReduceSum256(s2, sbuf);
    float scale = rsqrtf(s2 * (1.f / (float)PD) + PEPS);
    float* hr = h + (size_t)row * PD;
    #pragma unroll
    for (int i = 0; i < 4; i++)
        hr[i * 256 + t] = (v[i] - mean) * scale * g[i * 256 + t];
}

// ---------------------------------------------------------------------------
// Kernel 2: tf32 tensor-core GEMM  C[M,Nc] = A[M,K] * W[Nc,K]^T (+epilogue)
// 128x128 block tile, BK=16, 256 thr = 8 warps, each warp 64x32 via
// m16n8k8 tf32 mma. smem [128][20] (stride 20 -> conflict-free frag loads),
// double buffered.
// EPI=0: C = acc + bias
// EPI=1: C = xres + sigmoid(acc + bias) * t1
// ---------------------------------------------------------------------------
#define SMS 20   // smem row stride (floats)

template<int EPI>
__global__ __launch_bounds__(256) void mma_nt(
    const float* __restrict__ A, const float* __restrict__ W,
    const float* __restrict__ bias, float* __restrict__ C,
    int M, int Nc, int K,
    const float* __restrict__ xres, const float* __restrict__ t1)
{
    __shared__ float As[2][128][SMS];
    __shared__ float Bs[2][128][SMS];

    int tid = threadIdx.x, lane = tid & 31, wid = tid >> 5;
    int m0 = blockIdx.y * 128, n0 = blockIdx.x * 128;
    int wm = (wid & 1) * 64, wn = (wid >> 1) * 32;

    int lr = tid >> 1;          // row within tile, 0..127
    int lk = (tid & 1) * 8;     // k offset, 0 or 8

    float acc[4][4][4];
    #pragma unroll
    for (int mt = 0; mt < 4; mt++)
        #pragma unroll
        for (int nt = 0; nt < 4; nt++)
            #pragma unroll
            for (int c = 0; c < 4; c++) acc[mt][nt][c] = 0.f;

    bool aval = (m0 + lr) < M;
    const float* Aptr = A + (size_t)(m0 + lr) * K + lk;
    const float* Wptr = W + (size_t)(n0 + lr) * K + lk;

    float4 ra0 = aval ? *(const float4*)(Aptr)     : make_float4(0,0,0,0);
    float4 ra1 = aval ? *(const float4*)(Aptr + 4) : make_float4(0,0,0,0);
    float4 rw0 = *(const float4*)(Wptr);
    float4 rw1 = *(const float4*)(Wptr + 4);

    int gq = lane >> 2;   // group id 0..7
    int gt = lane & 3;    // thread-in-group 0..3

    for (int k0 = 0; k0 < K; k0 += 16) {
        int buf = (k0 >> 4) & 1;
        // store stage (tf32-rounded)
        {
            float4 t0 = make_float4(to_tf32(ra0.x), to_tf32(ra0.y), to_tf32(ra0.z), to_tf32(ra0.w));
            float4 t1v= make_float4(to_tf32(ra1.x), to_tf32(ra1.y), to_tf32(ra1.z), to_tf32(ra1.w));
            *(float4*)&As[buf][lr][lk]     = t0;
            *(float4*)&As[buf][lr][lk + 4] = t1v;
            float4 u0 = make_float4(to_tf32(rw0.x), to_tf32(rw0.y), to_tf32(rw0.z), to_tf32(rw0.w));
            float4 u1 = make_float4(to_tf32(rw1.x), to_tf32(rw1.y), to_tf32(rw1.z), to_tf32(rw1.w));
            *(float4*)&Bs[buf][lr][lk]     = u0;
            *(float4*)&Bs[buf][lr][lk + 4] = u1;
        }
        __syncthreads();

        // prefetch next stage
        if (k0 + 16 < K) {
            ra0 = aval ? *(const float4*)(Aptr + k0 + 16)     : make_float4(0,0,0,0);
            ra1 = aval ? *(const float4*)(Aptr + k0 + 16 + 4) : make_float4(0,0,0,0);
            rw0 = *(const float4*)(Wptr + k0 + 16);
            rw1 = *(const float4*)(Wptr + k0 + 16 + 4);
        }

        // two k-steps of 8
        #pragma unroll
        for (int kk = 0; kk < 16; kk += 8) {
            unsigned af[4][4], bf[4][2];
            #pragma unroll
            for (int mt = 0; mt < 4; mt++) {
                int mm = wm + mt * 16 + gq;
                af[mt][0] = __float_as_uint(As[buf][mm    ][kk + gt]);
                af[mt][1] = __float_as_uint(As[buf][mm + 8][kk + gt]);
                af[mt][2] = __float_as_uint(As[buf][mm    ][kk + gt + 4]);
                af[mt][3] = __float_as_uint(As[buf][mm + 8][kk + gt + 4]);
            }
            #pragma unroll
            for (int nt = 0; nt < 4; nt++) {
                int nn = wn + nt * 8 + gq;
                bf[nt][0] = __float_as_uint(Bs[buf][nn][kk + gt]);
                bf[nt][1] = __float_as_uint(Bs[buf][nn][kk + gt + 4]);
            }
            #pragma unroll
            for (int mt = 0; mt < 4; mt++)
                #pragma unroll
                for (int nt = 0; nt < 4; nt++) {
                    float* c = acc[mt][nt];
                    asm volatile(
                        "mma.sync.aligned.m16n8k8.row.col.f32.tf32.tf32.f32 "
                        "{%0,%1,%2,%3}, {%4,%5,%6,%7}, {%8,%9}, {%0,%1,%2,%3};"
                        : "+f"(c[0]), "+f"(c[1]), "+f"(c[2]), "+f"(c[3])
                        : "r"(af[mt][0]), "r"(af[mt][1]), "r"(af[mt][2]), "r"(af[mt][3]),
                          "r"(bf[nt][0]), "r"(bf[nt][1]));
                }
        }
        __syncthreads();
    }

    // epilogue: c0: (r, cb), c1: (r, cb+1), c2: (r+8, cb), c3: (r+8, cb+1)
    #pragma unroll
    for (int mt = 0; mt < 4; mt++) {
        int r0 = m0 + wm + mt * 16 + gq;
        #pragma unroll
        for (int nt = 0; nt < 4; nt++) {
            int cb = n0 + wn + nt * 8 + gt * 2;
            float b0 = bias[cb], b1 = bias[cb + 1];
            #pragma unroll
            for (int half = 0; half < 2; half++) {
                int r = r0 + half * 8;
                if (r >= M) continue;
                size_t off = (size_t)r * Nc + cb;
                float v0 = acc[mt][nt][half * 2 + 0] + b0;
                float v1 = acc[mt][nt][half * 2 + 1] + b1;
                if (EPI == 0) {
                    C[off] = v0; C[off + 1] = v1;
                } else {
                    float g0 = 1.f / (1.f + __expf(-v0));
                    float g1 = 1.f / (1.f + __expf(-v1));
                    C[off]     = xres[off]     + g0 * t1[off];
                    C[off + 1] = xres[off + 1] + g1 * t1[off + 1];
                }
            }
        }
    }
}

// ---------------------------------------------------------------------------
// Kernel 3: RoPE applied in place to q,k portions of qkv
// ---------------------------------------------------------------------------
__global__ __launch_bounds__(256) void rope_kernel(
    float* __restrict__ qkv, const float* __restrict__ fc)
{
    int idx = blockIdx.x * blockDim.x + threadIdx.x;
    const int total = PM * PH * (PDh / 2);
    if (idx >= total) return;
    int d2  = idx & 31;
    int h   = (idx >> 5) & 15;
    int row = idx >> 9;
    int n   = row % PN;
    float fr = fc[(n * 32 + d2) * 2 + 0];
    float fi = fc[(n * 32 + d2) * 2 + 1];
    size_t base = (size_t)row * 3072 + h * 64 + d2 * 2;
    float2 q = *(float2*)(qkv + base);
    *(float2*)(qkv + base) = make_float2(q.x * fr - q.y * fi, q.x * fi + q.y * fr);
    float2 k = *(float2*)(qkv + base + 1024);
    *(float2*)(qkv + base + 1024) = make_float2(k.x * fr - k.y * fi, k.x * fi + k.y * fr);
}

// ---------------------------------------------------------------------------
// Kernel 4: flash attention with additive bias (unchanged from R3)
// ---------------------------------------------------------------------------
__global__ __launch_bounds__(256) void flash_kernel(
    const float* __restrict__ qkv, const float* __restrict__ Bbias,
    float* __restrict__ y)
{
    extern __shared__ float sm[];
    float* Qs  = sm;
    float* Ks  = sm + 4160;
    float* Vs  = sm + 2 * 4160;
    float* Ss  = sm + 3 * 4160;
    float* m_s = sm + 4 * 4160;
    float* l_s = m_s + 64;
    float* c_s = l_s + 64;

    int b = blockIdx.z, h = blockIdx.y, q0 = blockIdx.x * 64;
    int tid = threadIdx.x, tx = tid & 15, ty = tid >> 4;

    for (int idx = tid; idx < 64 * 64; idx += 256) {
        int r = idx >> 6, d = idx & 63;
        int qr = q0 + r;
        Qs[r * 65 + d] = (qr < PN)
            ? qkv[((size_t)(b * PN + qr)) * 3072 + h * 64 + d] * 0.125f : 0.f;
    }
    if (tid < 64) { m_s[tid] = -1e30f; l_s[tid] = 0.f; }
    float acc[4][4] = {};
    __syncthreads();

    for (int k0 = 0; k0 < PN; k0 += 64) {
        for (int idx = tid; idx < 64 * 64; idx += 256) {
            int r = idx >> 6, d = idx & 63;
            int kr = k0 + r;
            if (kr < PN) {
                size_t base = ((size_t)(b * PN + kr)) * 3072 + h * 64 + d;
                Ks[r * 65 + d] = qkv[base + 1024];
                Vs[r * 65 + d] = qkv[base + 2048];
            } else {
                Ks[r * 65 + d] = 0.f; Vs[r * 65 + d] = 0.f;
            }
        }
        __syncthreads();

        float s[4][4] = {};
        #pragma unroll 4
        for (int d = 0; d < 64; d++) {
            float ra[4], rb[4];
            #pragma unroll
            for (int i = 0; i < 4; i++) ra[i] = Qs[(ty * 4 + i) * 65 + d];
            #pragma unroll
            for (int j = 0; j < 4; j++) rb[j] = Ks[(tx * 4 + j) * 65 + d];
            #pragma unroll
            for (int i = 0; i < 4; i++)
                #pragma unroll
                for (int j = 0; j < 4; j++) s[i][j] += ra[i] * rb[j];
        }

        #pragma unroll
        for (int i = 0; i < 4; i++) {
            int gr = q0 + ty * 4 + i;
            #pragma unroll
            for (int j = 0; j < 4; j++) {
                int gc = k0 + tx * 4 + j;
                float v;
                if (gc < PN) {
                    v = s[i][j];
                    if (gr < PN) v += Bbias[(size_t)gr * PN + gc];
                } else v = -1e30f;
                Ss[(ty * 4 + i) * 65 + tx * 4 + j] = v;
            }
        }
        __syncthreads();

        {
            int row = tid >> 2, seg = tid & 3;
            float mx = -1e30f;
            #pragma unroll
            for (int e = 0; e < 16; e++)
                mx = fmaxf(mx, Ss[row * 65 + seg * 16 + e]);
            mx = fmaxf(mx, __shfl_xor_sync(0xffffffffu, mx, 1));
            mx = fmaxf(mx, __shfl_xor_sync(0xffffffffu, mx, 2));
            float m_old = m_s[row];
            float m_new = fmaxf(m_old, mx);
            float sum = 0.f;
            #pragma unroll
            for (int e = 0; e < 16; e++) {
                float p = __expf(Ss[row * 65 + seg * 16 + e] - m_new);
                Ss[row * 65 + seg * 16 + e] = p;
                sum += p;
            }
            sum += __shfl_xor_sync(0xffffffffu, sum, 1);
            sum += __shfl_xor_sync(0xffffffffu, sum, 2);
            if (seg == 0) {
                float corr = __expf(m_old - m_new);
                c_s[row] = corr;
                l_s[row] = l_s[row] * corr + sum;
                m_s[row] = m_new;
            }
        }
        __syncthreads();

        float cr[4];
        #pragma unroll
        for (int i = 0; i < 4; i++) cr[i] = c_s[ty * 4 + i];
        #pragma unroll
        for (int i = 0; i < 4; i++)
            #pragma unroll
            for (int j = 0; j < 4; j++) acc[i][j] *= cr[i];
        #pragma unroll 4
        for (int kk = 0; kk < 64; kk++) {
            float rp[4], rv[4];
            #pragma unroll
            for (int i = 0; i < 4; i++) rp[i] = Ss[(ty * 4 + i) * 65 + kk];
            #pragma unroll
            for (int j = 0; j < 4; j++) rv[j] = Vs[kk * 65 + tx * 4 + j];
            #pragma unroll
            for (int i = 0; i < 4; i++)
                #pragma unroll
                for (int j = 0; j < 4; j++) acc[i][j] += rp[i] * rv[j];
        }
        __syncthreads();
    }

    #pragma unroll
    for (int i = 0; i < 4; i++) {
        int gr = q0 + ty * 4 + i;
        if (gr >= PN) continue;
        float inv = 1.f / l_s[ty * 4 + i];
        #pragma unroll
        for (int j = 0; j < 4; j++)
            y[((size_t)(b * PN + gr)) * PD + h * 64 + tx * 4 + j] = acc[i][j] * inv;
    }
}

// ---------------------------------------------------------------------------
// Launch
// ---------------------------------------------------------------------------
extern "C" void kernel_launch(void* const* d_in, const int* in_sizes, int n_in,
                              void* d_out, int out_size)
{
    (void)in_sizes; (void)n_in; (void)out_size;
    const float* x      = (const float*)d_in[0];
    const float* fc     = (const float*)d_in[1];
    const float* g      = (const float*)d_in[2];
    const float* qkv_w  = (const float*)d_in[3];
    const float* qkv_b  = (const float*)d_in[4];
    const float* out_w  = (const float*)d_in[5];
    const float* out_b  = (const float*)d_in[6];
    const float* gate_w = (const float*)d_in[7];
    const float* gate_b = (const float*)d_in[8];
    const float* Bbias  = (const float*)d_in[9];
    float* out = (float*)d_out;

    float *h, *qkv, *y, *t1;
    cudaGetSymbolAddress((void**)&h,   g_h);
    cudaGetSymbolAddress((void**)&qkv, g_qkv);
    cudaGetSymbolAddress((void**)&y,   g_y);
    cudaGetSymbolAddress((void**)&t1,  g_t1);

    // 1. zero-centered RMSNorm
    rmsnorm_kernel<<<PM, 256>>>(x, g, h);

    // 2. QKV projection (tf32 tensor cores)
    dim3 g1(3072 / 128, (PM + 127) / 128);
    mma_nt<0><<<g1, 256>>>(h, qkv_w, qkv_b, qkv, PM, 3072, PD, nullptr, nullptr);

    // 3. RoPE on q,k
    int nrope = PM * PH * (PDh / 2);
    rope_kernel<<<(nrope + 255) / 256, 256>>>(qkv, fc);

    // 4. flash attention
    cudaFuncSetAttribute(flash_kernel,
                         cudaFuncAttributeMaxDynamicSharedMemorySize, 67328);
    flash_kernel<<<dim3((PN + 63) / 64, PH, PB), 256, 67328>>>(qkv, Bbias, y);

    // 5. out projection: t1 = y @ out_w^T + out_b
    dim3 g2(PD / 128, (PM + 127) / 128);
    mma_nt<0><<<g2, 256>>>(y, out_w, out_b, t1, PM, PD, PD, nullptr, nullptr);

    // 6. gated residual: out = x + sigmoid(h @ gate_w^T + gate_b) * t1
    mma_nt<1><<<g2, 256>>>(h, gate_w, gate_b, out, PM, PD, PD, x, t1);
}

// round 6
// speedup vs baseline: 2.3718x; 1.5479x over previous
#include <cuda_runtime.h>
#include <math.h>

// Problem constants
#define PB 8
#define PN 1025
#define PD 1024
#define PH 16
#define PDh 64
#define PM (PB*PN)      // 8200 rows
#define PEPS 1e-8f

// Scratch (device globals: allocation-free rule)
__device__ float g_h  [(size_t)PM * PD];
__device__ float g_qkv[(size_t)PM * 3 * PD];
__device__ float g_y  [(size_t)PM * PD];
__device__ float g_t1 [(size_t)PM * PD];

__device__ __forceinline__ float to_tf32(float x) {
    float r;
    asm("cvt.rna.tf32.f32 %0, %1;" : "=f"(r) : "f"(x));
    return r;
}

// ---------------------------------------------------------------------------
// Block reduction helper (256 threads)
// ---------------------------------------------------------------------------
__device__ __forceinline__ float blockReduceSum256(float v, float* sbuf) {
    __syncthreads();
    int lane = threadIdx.x & 31, wid = threadIdx.x >> 5;
    #pragma unroll
    for (int o = 16; o > 0; o >>= 1) v += __shfl_xor_sync(0xffffffffu, v, o);
    if (lane == 0) sbuf[wid] = v;
    __syncthreads();
    float r = 0.f;
    #pragma unroll
    for (int w = 0; w < 8; w++) r += sbuf[w];
    return r;
}

// ---------------------------------------------------------------------------
// Kernel 1: zero-centered RMSNorm
// ---------------------------------------------------------------------------
__global__ __launch_bounds__(256) void rmsnorm_kernel(
    const float* __restrict__ x, const float* __restrict__ g,
    float* __restrict__ h)
{
    __shared__ float sbuf[8];
    int row = blockIdx.x;
    const float* xr = x + (size_t)row * PD;
    int t = threadIdx.x;
    float v[4];
    float s = 0.f;
    #pragma unroll
    for (int i = 0; i < 4; i++) { v[i] = xr[i * 256 + t]; s += v[i]; }
    s = blockReduceSum256(s, sbuf);
    float mean = s * (1.f / (float)PD);
    float s2 = 0.f;
    #pragma unroll
    for (int i = 0; i < 4; i++) { float c = v[i] - mean; s2 += c * c; }
    s2 = blockReduceSum256(s2, sbuf);
    float scale = rsqrtf(s2 * (1.f / (float)PD) + PEPS);
    float* hr = h + (size_t)row * PD;
    #pragma unroll
    for (int i = 0; i < 4; i++)
        hr[i * 256 + t] = (v[i] - mean) * scale * g[i * 256 + t];
}

// ---------------------------------------------------------------------------
// Kernel 2: tf32 tensor-core GEMM (proven in R4)
// ---------------------------------------------------------------------------
#define SMS 20

template<int EPI>
__global__ __launch_bounds__(256) void mma_nt(
    const float* __restrict__ A, const float* __restrict__ W,
    const float* __restrict__ bias, float* __restrict__ C,
    int M, int Nc, int K,
    const float* __restrict__ xres, const float* __restrict__ t1)
{
    __shared__ float As[2][128][SMS];
    __shared__ float Bs[2][128][SMS];

    int tid = threadIdx.x, lane = tid & 31, wid = tid >> 5;
    int m0 = blockIdx.y * 128, n0 = blockIdx.x * 128;
    int wm = (wid & 1) * 64, wn = (wid >> 1) * 32;

    int lr = tid >> 1;
    int lk = (tid & 1) * 8;

    float acc[4][4][4];
    #pragma unroll
    for (int mt = 0; mt < 4; mt++)
        #pragma unroll
        for (int nt = 0; nt < 4; nt++)
            #pragma unroll
            for (int c = 0; c < 4; c++) acc[mt][nt][c] = 0.f;

    bool aval = (m0 + lr) < M;
    const float* Aptr = A + (size_t)(m0 + lr) * K + lk;
    const float* Wptr = W + (size_t)(n0 + lr) * K + lk;

    float4 ra0 = aval ? *(const float4*)(Aptr)     : make_float4(0,0,0,0);
    float4 ra1 = aval ? *(const float4*)(Aptr + 4) : make_float4(0,0,0,0);
    float4 rw0 = *(const float4*)(Wptr);
    float4 rw1 = *(const float4*)(Wptr + 4);

    int gq = lane >> 2;
    int gt = lane & 3;

    for (int k0 = 0; k0 < K; k0 += 16) {
        int buf = (k0 >> 4) & 1;
        {
            float4 t0 = make_float4(to_tf32(ra0.x), to_tf32(ra0.y), to_tf32(ra0.z), to_tf32(ra0.w));
            float4 t1v= make_float4(to_tf32(ra1.x), to_tf32(ra1.y), to_tf32(ra1.z), to_tf32(ra1.w));
            *(float4*)&As[buf][lr][lk]     = t0;
            *(float4*)&As[buf][lr][lk + 4] = t1v;
            float4 u0 = make_float4(to_tf32(rw0.x), to_tf32(rw0.y), to_tf32(rw0.z), to_tf32(rw0.w));
            float4 u1 = make_float4(to_tf32(rw1.x), to_tf32(rw1.y), to_tf32(rw1.z), to_tf32(rw1.w));
            *(float4*)&Bs[buf][lr][lk]     = u0;
            *(float4*)&Bs[buf][lr][lk + 4] = u1;
        }
        __syncthreads();

        if (k0 + 16 < K) {
            ra0 = aval ? *(const float4*)(Aptr + k0 + 16)     : make_float4(0,0,0,0);
            ra1 = aval ? *(const float4*)(Aptr + k0 + 16 + 4) : make_float4(0,0,0,0);
            rw0 = *(const float4*)(Wptr + k0 + 16);
            rw1 = *(const float4*)(Wptr + k0 + 16 + 4);
        }

        #pragma unroll
        for (int kk = 0; kk < 16; kk += 8) {
            unsigned af[4][4], bf[4][2];
            #pragma unroll
            for (int mt = 0; mt < 4; mt++) {
                int mm = wm + mt * 16 + gq;
                af[mt][0] = __float_as_uint(As[buf][mm    ][kk + gt]);
                af[mt][1] = __float_as_uint(As[buf][mm + 8][kk + gt]);
                af[mt][2] = __float_as_uint(As[buf][mm    ][kk + gt + 4]);
                af[mt][3] = __float_as_uint(As[buf][mm + 8][kk + gt + 4]);
            }
            #pragma unroll
            for (int nt = 0; nt < 4; nt++) {
                int nn = wn + nt * 8 + gq;
                bf[nt][0] = __float_as_uint(Bs[buf][nn][kk + gt]);
                bf[nt][1] = __float_as_uint(Bs[buf][nn][kk + gt + 4]);
            }
            #pragma unroll
            for (int mt = 0; mt < 4; mt++)
                #pragma unroll
                for (int nt = 0; nt < 4; nt++) {
                    float* c = acc[mt][nt];
                    asm volatile(
                        "mma.sync.aligned.m16n8k8.row.col.f32.tf32.tf32.f32 "
                        "{%0,%1,%2,%3}, {%4,%5,%6,%7}, {%8,%9}, {%0,%1,%2,%3};"
                        : "+f"(c[0]), "+f"(c[1]), "+f"(c[2]), "+f"(c[3])
                        : "r"(af[mt][0]), "r"(af[mt][1]), "r"(af[mt][2]), "r"(af[mt][3]),
                          "r"(bf[nt][0]), "r"(bf[nt][1]));
                }
        }
        __syncthreads();
    }

    #pragma unroll
    for (int mt = 0; mt < 4; mt++) {
        int r0 = m0 + wm + mt * 16 + gq;
        #pragma unroll
        for (int nt = 0; nt < 4; nt++) {
            int cb = n0 + wn + nt * 8 + gt * 2;
            float b0 = bias[cb], b1 = bias[cb + 1];
            #pragma unroll
            for (int half = 0; half < 2; half++) {
                int r = r0 + half * 8;
                if (r >= M) continue;
                size_t off = (size_t)r * Nc + cb;
                float v0 = acc[mt][nt][half * 2 + 0] + b0;
                float v1 = acc[mt][nt][half * 2 + 1] + b1;
                if (EPI == 0) {
                    C[off] = v0; C[off + 1] = v1;
                } else {
                    float g0 = 1.f / (1.f + __expf(-v0));
                    float g1 = 1.f / (1.f + __expf(-v1));
                    C[off]     = xres[off]     + g0 * t1[off];
                    C[off + 1] = xres[off + 1] + g1 * t1[off + 1];
                }
            }
        }
    }
}

// ---------------------------------------------------------------------------
// Kernel 3: RoPE applied in place to q,k portions of qkv
// ---------------------------------------------------------------------------
__global__ __launch_bounds__(256) void rope_kernel(
    float* __restrict__ qkv, const float* __restrict__ fc)
{
    int idx = blockIdx.x * blockDim.x + threadIdx.x;
    const int total = PM * PH * (PDh / 2);
    if (idx >= total) return;
    int d2  = idx & 31;
    int h   = (idx >> 5) & 15;
    int row = idx >> 9;
    int n   = row % PN;
    float fr = fc[(n * 32 + d2) * 2 + 0];
    float fi = fc[(n * 32 + d2) * 2 + 1];
    size_t base = (size_t)row * 3072 + h * 64 + d2 * 2;
    float2 q = *(float2*)(qkv + base);
    *(float2*)(qkv + base) = make_float2(q.x * fr - q.y * fi, q.x * fi + q.y * fr);
    float2 k = *(float2*)(qkv + base + 1024);
    *(float2*)(qkv + base + 1024) = make_float2(k.x * fr - k.y * fi, k.x * fi + k.y * fr);
}

// ---------------------------------------------------------------------------
// Kernel 4: tensor-core flash attention (tf32 m16n8k8).
// Block 256 thr = 8 warps; q-tile 128 (16 rows/warp), k-tile 64, Dh 64.
// Q fragments live in registers across the whole loop. Softmax in registers.
// smem: Ks[64][68] + Vs[64][72] + Ps[128][68] = 70656 B (strides chosen
// so every mma fragment LDS is bank-conflict-free).
// ---------------------------------------------------------------------------
#define KS_STR 68
#define VS_STR 72
#define PS_STR 68

__global__ __launch_bounds__(256) void flash_mma_kernel(
    const float* __restrict__ qkv, const float* __restrict__ Bbias,
    float* __restrict__ y)
{
    extern __shared__ float sm[];
    float* Ks = sm;                              // [64][68]
    float* Vs = sm + 64 * KS_STR;                // [64][72]
    float* Ps = sm + 64 * KS_STR + 64 * VS_STR;  // [128][68]

    int b = blockIdx.z, h = blockIdx.y;
    int q0 = blockIdx.x * 128;
    int tid = threadIdx.x, lane = tid & 31, wid = tid >> 5;
    int gq = lane >> 2, gt = lane & 3;

    int wrow = wid * 16;            // warp's local row base
    int r1 = q0 + wrow + gq;        // global q rows
    int r2 = r1 + 8;
    bool r1ok = r1 < PN, r2ok = r2 < PN;

    // ---- load Q fragments into registers (scaled by 1/sqrt(Dh), tf32) ----
    unsigned qf[8][4];
    {
        const float* q1 = qkv + ((size_t)(b * PN + (r1ok ? r1 : 0))) * 3072 + h * 64;
        const float* q2 = qkv + ((size_t)(b * PN + (r2ok ? r2 : 0))) * 3072 + h * 64;
        #pragma unroll
        for (int ks = 0; ks < 8; ks++) {
            int c0 = ks * 8 + gt, c1 = c0 + 4;
            qf[ks][0] = r1ok ? __float_as_uint(to_tf32(__ldg(q1 + c0) * 0.125f)) : 0u;
            qf[ks][1] = r2ok ? __float_as_uint(to_tf32(__ldg(q2 + c0) * 0.125f)) : 0u;
            qf[ks][2] = r1ok ? __float_as_uint(to_tf32(__ldg(q1 + c1) * 0.125f)) : 0u;
            qf[ks][3] = r2ok ? __float_as_uint(to_tf32(__ldg(q2 + c1) * 0.125f)) : 0u;
        }
    }

    float oacc[8][4];
    #pragma unroll
    for (int nt = 0; nt < 8; nt++)
        #pragma unroll
        for (int c = 0; c < 4; c++) oacc[nt][c] = 0.f;
    float m1 = -1e30f, m2 = -1e30f, l1 = 0.f, l2 = 0.f;

    for (int k0 = 0; k0 < PN; k0 += 64) {
        // ---- load K,V tiles (tf32-rounded) ----
        for (int i = tid; i < 64 * 16; i += 256) {
            int kr = i >> 4, dg = (i & 15) << 2;
            int gk = k0 + kr;
            float4 kv = make_float4(0,0,0,0), vv = make_float4(0,0,0,0);
            if (gk < PN) {
                const float* base = qkv + ((size_t)(b * PN + gk)) * 3072 + h * 64 + dg;
                kv = *(const float4*)(base + 1024);
                vv = *(const float4*)(base + 2048);
            }
            float* kd = &Ks[kr * KS_STR + dg];
            kd[0] = to_tf32(kv.x); kd[1] = to_tf32(kv.y);
            kd[2] = to_tf32(kv.z); kd[3] = to_tf32(kv.w);
            float* vd = &Vs[kr * VS_STR + dg];
            vd[0] = to_tf32(vv.x); vd[1] = to_tf32(vv.y);
            vd[2] = to_tf32(vv.z); vd[3] = to_tf32(vv.w);
        }
        __syncthreads();

        // ---- S = Q K^T ----
        float sacc[8][4];
        #pragma unroll
        for (int nt = 0; nt < 8; nt++)
            #pragma unroll
            for (int c = 0; c < 4; c++) sacc[nt][c] = 0.f;

        #pragma unroll
        for (int ks = 0; ks < 8; ks++) {
            int kk = ks * 8;
            #pragma unroll
            for (int nt = 0; nt < 8; nt++) {
                unsigned b0 = __float_as_uint(Ks[(nt * 8 + gq) * KS_STR + kk + gt]);
                unsigned b1 = __float_as_uint(Ks[(nt * 8 + gq) * KS_STR + kk + gt + 4]);
                float* c = sacc[nt];
                asm volatile(
                    "mma.sync.aligned.m16n8k8.row.col.f32.tf32.tf32.f32 "
                    "{%0,%1,%2,%3}, {%4,%5,%6,%7}, {%8,%9}, {%0,%1,%2,%3};"
                    : "+f"(c[0]), "+f"(c[1]), "+f"(c[2]), "+f"(c[3])
                    : "r"(qf[ks][0]), "r"(qf[ks][1]), "r"(qf[ks][2]), "r"(qf[ks][3]),
                      "r"(b0), "r"(b1));
            }
        }

        // ---- bias + mask + row max ----
        float mx1 = -1e30f, mx2 = -1e30f;
        const float* bb1 = Bbias + (size_t)(r1ok ? r1 : 0) * PN;
        const float* bb2 = Bbias + (size_t)(r2ok ? r2 : 0) * PN;
        #pragma unroll
        for (int nt = 0; nt < 8; nt++) {
            int gc0 = k0 + nt * 8 + gt * 2;
            int gc1 = gc0 + 1;
            bool c0ok = gc0 < PN, c1ok = gc1 < PN;
            sacc[nt][0] = (r1ok && c0ok) ? sacc[nt][0] + __ldg(bb1 + gc0) : -1e30f;
            sacc[nt][1] = (r1ok && c1ok) ? sacc[nt][1] + __ldg(bb1 + gc1) : -1e30f;
            sacc[nt][2] = (r2ok && c0ok) ? sacc[nt][2] + __ldg(bb2 + gc0) : -1e30f;
            sacc[nt][3] = (r2ok && c1ok) ? sacc[nt][3] + __ldg(bb2 + gc1) : -1e30f;
            mx1 = fmaxf(mx1, fmaxf(sacc[nt][0], sacc[nt][1]));
            mx2 = fmaxf(mx2, fmaxf(sacc[nt][2], sacc[nt][3]));
        }
        mx1 = fmaxf(mx1, __shfl_xor_sync(0xffffffffu, mx1, 1));
        mx1 = fmaxf(mx1, __shfl_xor_sync(0xffffffffu, mx1, 2));
        mx2 = fmaxf(mx2, __shfl_xor_sync(0xffffffffu, mx2, 1));
        mx2 = fmaxf(mx2, __shfl_xor_sync(0xffffffffu, mx2, 2));

        float mn1 = fmaxf(m1, mx1), mn2 = fmaxf(m2, mx2);
        float corr1 = __expf(m1 - mn1), corr2 = __expf(m2 - mn2);
        m1 = mn1; m2 = mn2;

        // ---- exp, row sums, store P ----
        float sum1 = 0.f, sum2 = 0.f;
        #pragma unroll
        for (int nt = 0; nt < 8; nt++) {
            float p0 = __expf(sacc[nt][0] - m1);
            float p1 = __expf(sacc[nt][1] - m1);
            float p2 = __expf(sacc[nt][2] - m2);
            float p3 = __expf(sacc[nt][3] - m2);
            sum1 += p0 + p1; sum2 += p2 + p3;
            int col = nt * 8 + gt * 2;
            *(float2*)&Ps[(wrow + gq)     * PS_STR + col] = make_float2(to_tf32(p0), to_tf32(p1));
            *(float2*)&Ps[(wrow + gq + 8) * PS_STR + col] = make_float2(to_tf32(p2), to_tf32(p3));
        }
        sum1 += __shfl_xor_sync(0xffffffffu, sum1, 1);
        sum1 += __shfl_xor_sync(0xffffffffu, sum1, 2);
        sum2 += __shfl_xor_sync(0xffffffffu, sum2, 1);
        sum2 += __shfl_xor_sync(0xffffffffu, sum2, 2);
        l1 = l1 * corr1 + sum1;
        l2 = l2 * corr2 + sum2;

        // ---- rescale O ----
        #pragma unroll
        for (int nt = 0; nt < 8; nt++) {
            oacc[nt][0] *= corr1; oacc[nt][1] *= corr1;
            oacc[nt][2] *= corr2; oacc[nt][3] *= corr2;
        }
        __syncwarp();   // warp reads back only its own Ps rows

        // ---- O += P V ----
        #pragma unroll
        for (int ks = 0; ks < 8; ks++) {
            int kk = ks * 8;
            unsigned a0 = __float_as_uint(Ps[(wrow + gq)     * PS_STR + kk + gt]);
            unsigned a1 = __float_as_uint(Ps[(wrow + gq + 8) * PS_STR + kk + gt]);
            unsigned a2 = __float_as_uint(Ps[(wrow + gq)     * PS_STR + kk + gt + 4]);
            unsigned a3 = __float_as_uint(Ps[(wrow + gq + 8) * PS_STR + kk + gt + 4]);
            #pragma unroll
            for (int nt = 0; nt < 8; nt++) {
                unsigned b0 = __float_as_uint(Vs[(kk + gt)     * VS_STR + nt * 8 + gq]);
                unsigned b1 = __float_as_uint(Vs[(kk + gt + 4) * VS_STR + nt * 8 + gq]);
                float* c = oacc[nt];
                asm volatile(
                    "mma.sync.aligned.m16n8k8.row.col.f32.tf32.tf32.f32 "
                    "{%0,%1,%2,%3}, {%4,%5,%6,%7}, {%8,%9}, {%0,%1,%2,%3};"
                    : "+f"(c[0]), "+f"(c[1]), "+f"(c[2]), "+f"(c[3])
                    : "r"(a0), "r"(a1), "r"(a2), "r"(a3),
                      "r"(b0), "r"(b1));
            }
        }
        __syncthreads();   // before overwriting Ks/Vs next tile
    }

    // ---- epilogue: normalize and write y[b, q, h*64 + d] ----
    float inv1 = 1.f / l1, inv2 = 1.f / l2;
    #pragma unroll
    for (int nt = 0; nt < 8; nt++) {
        int col = h * 64 + nt * 8 + gt * 2;
        if (r1ok) {
            float* dst = y + ((size_t)(b * PN + r1)) * PD + col;
            dst[0] = oacc[nt][0] * inv1;
            dst[1] = oacc[nt][1] * inv1;
        }
        if (r2ok) {
            float* dst = y + ((size_t)(b * PN + r2)) * PD + col;
            dst[0] = oacc[nt][2] * inv2;
            dst[1] = oacc[nt][3] * inv2;
        }
    }
}

#define FLASH_SMEM ((64*KS_STR + 64*VS_STR + 128*PS_STR) * 4)

// ---------------------------------------------------------------------------
// Launch
// ---------------------------------------------------------------------------
extern "C" void kernel_launch(void* const* d_in, const int* in_sizes, int n_in,
                              void* d_out, int out_size)
{
    (void)in_sizes; (void)n_in; (void)out_size;
    const float* x      = (const float*)d_in[0];
    const float* fc     = (const float*)d_in[1];
    const float* g      = (const float*)d_in[2];
    const float* qkv_w  = (const float*)d_in[3];
    const float* qkv_b  = (const float*)d_in[4];
    const float* out_w  = (const float*)d_in[5];
    const float* out_b  = (const float*)d_in[6];
    const float* gate_w = (const float*)d_in[7];
    const float* gate_b = (const float*)d_in[8];
    const float* Bbias  = (const float*)d_in[9];
    float* out = (float*)d_out;

    float *h, *qkv, *y, *t1;
    cudaGetSymbolAddress((void**)&h,   g_h);
    cudaGetSymbolAddress((void**)&qkv, g_qkv);
    cudaGetSymbolAddress((void**)&y,   g_y);
    cudaGetSymbolAddress((void**)&t1,  g_t1);

    // 1. zero-centered RMSNorm
    rmsnorm_kernel<<<PM, 256>>>(x, g, h);

    // 2. QKV projection (tf32 tensor cores)
    dim3 g1(3072 / 128, (PM + 127) / 128);
    mma_nt<0><<<g1, 256>>>(h, qkv_w, qkv_b, qkv, PM, 3072, PD, nullptr, nullptr);

    // 3. RoPE on q,k
    int nrope = PM * PH * (PDh / 2);
    rope_kernel<<<(nrope + 255) / 256, 256>>>(qkv, fc);

    // 4. tensor-core flash attention
    cudaFuncSetAttribute(flash_mma_kernel,
                         cudaFuncAttributeMaxDynamicSharedMemorySize, FLASH_SMEM);
    flash_mma_kernel<<<dim3((PN + 127) / 128, PH, PB), 256, FLASH_SMEM>>>(qkv, Bbias, y);

    // 5. out projection: t1 = y @ out_w^T + out_b
    dim3 g2(PD / 128, (PM + 127) / 128);
    mma_nt<0><<<g2, 256>>>(y, out_w, out_b, t1, PM, PD, PD, nullptr, nullptr);

    // 6. gated residual: out = x + sigmoid(h @ gate_w^T + gate_b) * t1
    mma_nt<1><<<g2, 256>>>(h, gate_w, gate_b, out, PM, PD, PD, x, t1);
}

// round 7
// speedup vs baseline: 3.1891x; 1.3446x over previous
#include <cuda_runtime.h>
#include <math.h>

// Problem constants
#define PB 8
#define PN 1025
#define PD 1024
#define PH 16
#define PDh 64
#define PM (PB*PN)      // 8200 rows
#define PEPS 1e-8f

// Scratch (device globals: allocation-free rule)
__device__ float g_h  [(size_t)PM * PD];
__device__ float g_qkv[(size_t)PM * 3 * PD];
__device__ float g_y  [(size_t)PM * PD];
__device__ float g_t1 [(size_t)PM * PD];

__device__ __forceinline__ float to_tf32(float x) {
    float r;
    asm("cvt.rna.tf32.f32 %0, %1;" : "=f"(r) : "f"(x));
    return r;
}

// cp.async helpers (16B, zero-fill when src_bytes < 16)
__device__ __forceinline__ void cp_async16(void* smem_dst, const void* gmem_src, int src_bytes) {
    unsigned saddr = (unsigned)__cvta_generic_to_shared(smem_dst);
    asm volatile("cp.async.cg.shared.global [%0], [%1], 16, %2;\n"
                 :: "r"(saddr), "l"(gmem_src), "r"(src_bytes));
}
__device__ __forceinline__ void cp_commit() {
    asm volatile("cp.async.commit_group;\n" ::);
}
template<int N>
__device__ __forceinline__ void cp_wait() {
    asm volatile("cp.async.wait_group %0;\n" :: "n"(N));
}

// ---------------------------------------------------------------------------
// Block reduction helper (256 threads)
// ---------------------------------------------------------------------------
__device__ __forceinline__ float blockReduceSum256(float v, float* sbuf) {
    __syncthreads();
    int lane = threadIdx.x & 31, wid = threadIdx.x >> 5;
    #pragma unroll
    for (int o = 16; o > 0; o >>= 1) v += __shfl_xor_sync(0xffffffffu, v, o);
    if (lane == 0) sbuf[wid] = v;
    __syncthreads();
    float r = 0.f;
    #pragma unroll
    for (int w = 0; w < 8; w++) r += sbuf[w];
    return r;
}

// ---------------------------------------------------------------------------
// Kernel 1: zero-centered RMSNorm
// ---------------------------------------------------------------------------
__global__ __launch_bounds__(256) void rmsnorm_kernel(
    const float* __restrict__ x, const float* __restrict__ g,
    float* __restrict__ h)
{
    __shared__ float sbuf[8];
    int row = blockIdx.x;
    const float* xr = x + (size_t)row * PD;
    int t = threadIdx.x;
    float v[4];
    float s = 0.f;
    #pragma unroll
    for (int i = 0; i < 4; i++) { v[i] = xr[i * 256 + t]; s += v[i]; }
    s = blockReduceSum256(s, sbuf);
    float mean = s * (1.f / (float)PD);
    float s2 = 0.f;
    #pragma unroll
    for (int i = 0; i < 4; i++) { float c = v[i] - mean; s2 += c * c; }
    s2 = blockReduceSum256(s2, sbuf);
    float scale = rsqrtf(s2 * (1.f / (float)PD) + PEPS);
    float* hr = h + (size_t)row * PD;
    #pragma unroll
    for (int i = 0; i < 4; i++)
        hr[i * 256 + t] = (v[i] - mean) * scale * g[i * 256 + t];
}

// ---------------------------------------------------------------------------
// Kernel 2: tf32 tensor-core GEMM, 3-stage cp.async pipeline.
// C[M,Nc] = A[M,K] * W[Nc,K]^T (+epilogue). 128x128 tile, BK=16,
// 256 thr = 8 warps (64x32 each). One __syncthreads per K-step.
// tf32 rounding: HW truncation inside mma.
// ---------------------------------------------------------------------------
#define SMS 20
#define GSTG 3
#define GEMM_SMEM (GSTG * 128 * SMS * 2 * 4)   // 61440 B

template<int EPI>
__global__ __launch_bounds__(256) void mma_nt(
    const float* __restrict__ A, const float* __restrict__ W,
    const float* __restrict__ bias, float* __restrict__ C,
    int M, int Nc, int K,
    const float* __restrict__ xres, const float* __restrict__ t1)
{
    extern __shared__ float smg[];
    float* As = smg;                       // [GSTG][128][SMS]
    float* Bs = smg + GSTG * 128 * SMS;    // [GSTG][128][SMS]

    int tid = threadIdx.x, lane = tid & 31, wid = tid >> 5;
    int m0 = blockIdx.y * 128, n0 = blockIdx.x * 128;
    int wm = (wid & 1) * 64, wn = (wid >> 1) * 32;

    int lr = tid >> 1;
    int lk = (tid & 1) * 8;
    int gq = lane >> 2, gt = lane & 3;

    float acc[4][4][4];
    #pragma unroll
    for (int mt = 0; mt < 4; mt++)
        #pragma unroll
        for (int nt = 0; nt < 4; nt++)
            #pragma unroll
            for (int c = 0; c < 4; c++) acc[mt][nt][c] = 0.f;

    bool aval = (m0 + lr) < M;
    int arow = aval ? (m0 + lr) : (M - 1);
    const float* Aptr = A + (size_t)arow * K + lk;
    const float* Wptr = W + (size_t)(n0 + lr) * K + lk;
    int abytes = aval ? 16 : 0;

    const int steps = K >> 4;   // K/16

    // prologue: stages 0 .. GSTG-2
    #pragma unroll
    for (int s = 0; s < GSTG - 1; s++) {
        int k0 = s * 16;
        cp_async16(&As[(s * 128 + lr) * SMS + lk],     Aptr + k0,     abytes);
        cp_async16(&As[(s * 128 + lr) * SMS + lk + 4], Aptr + k0 + 4, abytes);
        cp_async16(&Bs[(s * 128 + lr) * SMS + lk],     Wptr + k0,     16);
        cp_async16(&Bs[(s * 128 + lr) * SMS + lk + 4], Wptr + k0 + 4, 16);
        cp_commit();
    }

    for (int i = 0; i < steps; i++) {
        cp_wait<GSTG - 2>();
        __syncthreads();

        // prefetch stage i+GSTG-1
        int pf = i + GSTG - 1;
        if (pf < steps) {
            int s = pf % GSTG;
            int k0 = pf * 16;
            cp_async16(&As[(s * 128 + lr) * SMS + lk],     Aptr + k0,     abytes);
            cp_async16(&As[(s * 128 + lr) * SMS + lk + 4], Aptr + k0 + 4, abytes);
            cp_async16(&Bs[(s * 128 + lr) * SMS + lk],     Wptr + k0,     16);
            cp_async16(&Bs[(s * 128 + lr) * SMS + lk + 4], Wptr + k0 + 4, 16);
        }
        cp_commit();

        const float* Asb = As + (i % GSTG) * 128 * SMS;
        const float* Bsb = Bs + (i % GSTG) * 128 * SMS;

        #pragma unroll
        for (int kk = 0; kk < 16; kk += 8) {
            unsigned af[4][4], bf[4][2];
            #pragma unroll
            for (int mt = 0; mt < 4; mt++) {
                int mm = wm + mt * 16 + gq;
                af[mt][0] = __float_as_uint(Asb[ mm      * SMS + kk + gt]);
                af[mt][1] = __float_as_uint(Asb[(mm + 8) * SMS + kk + gt]);
                af[mt][2] = __float_as_uint(Asb[ mm      * SMS + kk + gt + 4]);
                af[mt][3] = __float_as_uint(Asb[(mm + 8) * SMS + kk + gt + 4]);
            }
            #pragma unroll
            for (int nt = 0; nt < 4; nt++) {
                int nn = wn + nt * 8 + gq;
                bf[nt][0] = __float_as_uint(Bsb[nn * SMS + kk + gt]);
                bf[nt][1] = __float_as_uint(Bsb[nn * SMS + kk + gt + 4]);
            }
            #pragma unroll
            for (int mt = 0; mt < 4; mt++)
                #pragma unroll
                for (int nt = 0; nt < 4; nt++) {
                    float* c = acc[mt][nt];
                    asm volatile(
                        "mma.sync.aligned.m16n8k8.row.col.f32.tf32.tf32.f32 "
                        "{%0,%1,%2,%3}, {%4,%5,%6,%7}, {%8,%9}, {%0,%1,%2,%3};"
                        : "+f"(c[0]), "+f"(c[1]), "+f"(c[2]), "+f"(c[3])
                        : "r"(af[mt][0]), "r"(af[mt][1]), "r"(af[mt][2]), "r"(af[mt][3]),
                          "r"(bf[nt][0]), "r"(bf[nt][1]));
                }
        }
    }

    #pragma unroll
    for (int mt = 0; mt < 4; mt++) {
        int r0 = m0 + wm + mt * 16 + gq;
        #pragma unroll
        for (int nt = 0; nt < 4; nt++) {
            int cb = n0 + wn + nt * 8 + gt * 2;
            float b0 = bias[cb], b1 = bias[cb + 1];
            #pragma unroll
            for (int half = 0; half < 2; half++) {
                int r = r0 + half * 8;
                if (r >= M) continue;
                size_t off = (size_t)r * Nc + cb;
                float v0 = acc[mt][nt][half * 2 + 0] + b0;
                float v1 = acc[mt][nt][half * 2 + 1] + b1;
                if (EPI == 0) {
                    C[off] = v0; C[off + 1] = v1;
                } else {
                    float g0 = 1.f / (1.f + __expf(-v0));
                    float g1 = 1.f / (1.f + __expf(-v1));
                    C[off]     = xres[off]     + g0 * t1[off];
                    C[off + 1] = xres[off + 1] + g1 * t1[off + 1];
                }
            }
        }
    }
}

// ---------------------------------------------------------------------------
// Kernel 3: RoPE applied in place to q,k portions of qkv
// ---------------------------------------------------------------------------
__global__ __launch_bounds__(256) void rope_kernel(
    float* __restrict__ qkv, const float* __restrict__ fc)
{
    int idx = blockIdx.x * blockDim.x + threadIdx.x;
    const int total = PM * PH * (PDh / 2);
    if (idx >= total) return;
    int d2  = idx & 31;
    int h   = (idx >> 5) & 15;
    int row = idx >> 9;
    int n   = row % PN;
    float fr = fc[(n * 32 + d2) * 2 + 0];
    float fi = fc[(n * 32 + d2) * 2 + 1];
    size_t base = (size_t)row * 3072 + h * 64 + d2 * 2;
    float2 q = *(float2*)(qkv + base);
    *(float2*)(qkv + base) = make_float2(q.x * fr - q.y * fi, q.x * fi + q.y * fr);
    float2 k = *(float2*)(qkv + base + 1024);
    *(float2*)(qkv + base + 1024) = make_float2(k.x * fr - k.y * fi, k.x * fi + k.y * fr);
}

// ---------------------------------------------------------------------------
// Kernel 4: tensor-core flash attention, 2-stage cp.async K/V double buffer.
// Block 256 thr = 8 warps; q-tile 128 (16 rows/warp), k-tile 64, Dh 64.
// ONE __syncthreads per k-tile (Ps is warp-private -> __syncwarp only).
// smem: Ks[2][64][68] + Vs[2][64][72] + Ps[128][68] = 106496 B
// ---------------------------------------------------------------------------
#define KS_STR 68
#define VS_STR 72
#define PS_STR 68
#define NKT ((PN + 63) / 64)    // 17 k-tiles
#define FLASH_SMEM ((2*64*KS_STR + 2*64*VS_STR + 128*PS_STR) * 4)

__global__ __launch_bounds__(256) void flash_mma_kernel(
    const float* __restrict__ qkv, const float* __restrict__ Bbias,
    float* __restrict__ y)
{
    extern __shared__ float sm[];
    float* Ks = sm;                                   // [2][64][68]
    float* Vs = sm + 2 * 64 * KS_STR;                 // [2][64][72]
    float* Ps = sm + 2 * 64 * KS_STR + 2 * 64 * VS_STR; // [128][68]

    int b = blockIdx.z, h = blockIdx.y;
    int q0 = blockIdx.x * 128;
    int tid = threadIdx.x, lane = tid & 31, wid = tid >> 5;
    int gq = lane >> 2, gt = lane & 3;

    int wrow = wid * 16;
    int r1 = q0 + wrow + gq;
    int r2 = r1 + 8;
    bool r1ok = r1 < PN, r2ok = r2 < PN;

    const float* qkv_bh = qkv + ((size_t)b * PN) * 3072 + h * 64;

    // ---- prologue: issue K/V stage 0 ----
    {
        for (int i = tid; i < 64 * 16; i += 256) {
            int kr = i >> 4, dg = (i & 15) << 2;
            int gk = kr;   // k0 = 0
            int ok = (gk < PN) ? 16 : 0;
            const float* base = qkv_bh + (size_t)((gk < PN) ? gk : (PN - 1)) * 3072 + dg;
            cp_async16(&Ks[kr * KS_STR + dg], base + 1024, ok);
            cp_async16(&Vs[kr * VS_STR + dg], base + 2048, ok);
        }
        cp_commit();
    }

    // ---- load Q fragments into registers (scaled by 1/sqrt(Dh), tf32) ----
    unsigned qf[8][4];
    {
        const float* q1 = qkv_bh + (size_t)(r1ok ? r1 : 0) * 3072;
        const float* q2 = qkv_bh + (size_t)(r2ok ? r2 : 0) * 3072;
        #pragma unroll
        for (int ks = 0; ks < 8; ks++) {
            int c0 = ks * 8 + gt, c1 = c0 + 4;
            qf[ks][0] = r1ok ? __float_as_uint(to_tf32(__ldg(q1 + c0) * 0.125f)) : 0u;
            qf[ks][1] = r2ok ? __float_as_uint(to_tf32(__ldg(q2 + c0) * 0.125f)) : 0u;
            qf[ks][2] = r1ok ? __float_as_uint(to_tf32(__ldg(q1 + c1) * 0.125f)) : 0u;
            qf[ks][3] = r2ok ? __float_as_uint(to_tf32(__ldg(q2 + c1) * 0.125f)) : 0u;
        }
    }

    float oacc[8][4];
    #pragma unroll
    for (int nt = 0; nt < 8; nt++)
        #pragma unroll
        for (int c = 0; c < 4; c++) oacc[nt][c] = 0.f;
    float m1 = -1e30f, m2 = -1e30f, l1 = 0.f, l2 = 0.f;

    const float* bb1 = Bbias + (size_t)(r1ok ? r1 : 0) * PN;
    const float* bb2 = Bbias + (size_t)(r2ok ? r2 : 0) * PN;

    for (int it = 0; it < NKT; it++) {
        int k0 = it * 64;
        cp_wait<0>();
        __syncthreads();   // stage (it&1) ready for all; all warps done with prev tile

        // prefetch next stage
        if (it + 1 < NKT) {
            int s = (it + 1) & 1;
            int nk0 = (it + 1) * 64;
            for (int i = tid; i < 64 * 16; i += 256) {
                int kr = i >> 4, dg = (i & 15) << 2;
                int gk = nk0 + kr;
                int ok = (gk < PN) ? 16 : 0;
                const float* base = qkv_bh + (size_t)((gk < PN) ? gk : (PN - 1)) * 3072 + dg;
                cp_async16(&Ks[(s * 64 + kr) * KS_STR + dg], base + 1024, ok);
                cp_async16(&Vs[(s * 64 + kr) * VS_STR + dg], base + 2048, ok);
            }
        }
        cp_commit();

        const float* Ksb = Ks + (it & 1) * 64 * KS_STR;
        const float* Vsb = Vs + (it & 1) * 64 * VS_STR;

        // ---- S = Q K^T ----
        float sacc[8][4];
        #pragma unroll
        for (int nt = 0; nt < 8; nt++)
            #pragma unroll
            for (int c = 0; c < 4; c++) sacc[nt][c] = 0.f;

        #pragma unroll
        for (int ks = 0; ks < 8; ks++) {
            int kk = ks * 8;
            #pragma unroll
            for (int nt = 0; nt < 8; nt++) {
                unsigned b0 = __float_as_uint(Ksb[(nt * 8 + gq) * KS_STR + kk + gt]);
                unsigned b1 = __float_as_uint(Ksb[(nt * 8 + gq) * KS_STR + kk + gt + 4]);
                float* c = sacc[nt];
                asm volatile(
                    "mma.sync.aligned.m16n8k8.row.col.f32.tf32.tf32.f32 "
                    "{%0,%1,%2,%3}, {%4,%5,%6,%7}, {%8,%9}, {%0,%1,%2,%3};"
                    : "+f"(c[0]), "+f"(c[1]), "+f"(c[2]), "+f"(c[3])
                    : "r"(qf[ks][0]), "r"(qf[ks][1]), "r"(qf[ks][2]), "r"(qf[ks][3]),
                      "r"(b0), "r"(b1));
            }
        }

        // ---- bias + mask + row max ----
        float mx1 = -1e30f, mx2 = -1e30f;
        #pragma unroll
        for (int nt = 0; nt < 8; nt++) {
            int gc0 = k0 + nt * 8 + gt * 2;
            int gc1 = gc0 + 1;
            bool c0ok = gc0 < PN, c1ok = gc1 < PN;
            sacc[nt][0] = (r1ok && c0ok) ? sacc[nt][0] + __ldg(bb1 + gc0) : -1e30f;
            sacc[nt][1] = (r1ok && c1ok) ? sacc[nt][1] + __ldg(bb1 + gc1) : -1e30f;
            sacc[nt][2] = (r2ok && c0ok) ? sacc[nt][2] + __ldg(bb2 + gc0) : -1e30f;
            sacc[nt][3] = (r2ok && c1ok) ? sacc[nt][3] + __ldg(bb2 + gc1) : -1e30f;
            mx1 = fmaxf(mx1, fmaxf(sacc[nt][0], sacc[nt][1]));
            mx2 = fmaxf(mx2, fmaxf(sacc[nt][2], sacc[nt][3]));
        }
        mx1 = fmaxf(mx1, __shfl_xor_sync(0xffffffffu, mx1, 1));
        mx1 = fmaxf(mx1, __shfl_xor_sync(0xffffffffu, mx1, 2));
        mx2 = fmaxf(mx2, __shfl_xor_sync(0xffffffffu, mx2, 1));
        mx2 = fmaxf(mx2, __shfl_xor_sync(0xffffffffu, mx2, 2));

        float mn1 = fmaxf(m1, mx1), mn2 = fmaxf(m2, mx2);
        float corr1 = __expf(m1 - mn1), corr2 = __expf(m2 - mn2);
        m1 = mn1; m2 = mn2;

        // ---- exp, row sums, store P ----
        float sum1 = 0.f, sum2 = 0.f;
        #pragma unroll
        for (int nt = 0; nt < 8; nt++) {
            float p0 = __expf(sacc[nt][0] - m1);
            float p1 = __expf(sacc[nt][1] - m1);
            float p2 = __expf(sacc[nt][2] - m2);
            float p3 = __expf(sacc[nt][3] - m2);
            sum1 += p0 + p1; sum2 += p2 + p3;
            int col = nt * 8 + gt * 2;
            *(float2*)&Ps[(wrow + gq)     * PS_STR + col] = make_float2(to_tf32(p0), to_tf32(p1));
            *(float2*)&Ps[(wrow + gq + 8) * PS_STR + col] = make_float2(to_tf32(p2), to_tf32(p3));
        }
        sum1 += __shfl_xor_sync(0xffffffffu, sum1, 1);
        sum1 += __shfl_xor_sync(0xffffffffu, sum1, 2);
        sum2 += __shfl_xor_sync(0xffffffffu, sum2, 1);
        sum2 += __shfl_xor_sync(0xffffffffu, sum2, 2);
        l1 = l1 * corr1 + sum1;
        l2 = l2 * corr2 + sum2;

        // ---- rescale O ----
        #pragma unroll
        for (int nt = 0; nt < 8; nt++) {
            oacc[nt][0] *= corr1; oacc[nt][1] *= corr1;
            oacc[nt][2] *= corr2; oacc[nt][3] *= corr2;
        }
        __syncwarp();   // warp reads back only its own Ps rows

        // ---- O += P V ----
        #pragma unroll
        for (int ks = 0; ks < 8; ks++) {
            int kk = ks * 8;
            unsigned a0 = __float_as_uint(Ps[(wrow + gq)     * PS_STR + kk + gt]);
            unsigned a1 = __float_as_uint(Ps[(wrow + gq + 8) * PS_STR + kk + gt]);
            unsigned a2 = __float_as_uint(Ps[(wrow + gq)     * PS_STR + kk + gt + 4]);
            unsigned a3 = __float_as_uint(Ps[(wrow + gq + 8) * PS_STR + kk + gt + 4]);
            #pragma unroll
            for (int nt = 0; nt < 8; nt++) {
                unsigned b0 = __float_as_uint(Vsb[(kk + gt)     * VS_STR + nt * 8 + gq]);
                unsigned b1 = __float_as_uint(Vsb[(kk + gt + 4) * VS_STR + nt * 8 + gq]);
                float* c = oacc[nt];
                asm volatile(
                    "mma.sync.aligned.m16n8k8.row.col.f32.tf32.tf32.f32 "
                    "{%0,%1,%2,%3}, {%4,%5,%6,%7}, {%8,%9}, {%0,%1,%2,%3};"
                    : "+f"(c[0]), "+f"(c[1]), "+f"(c[2]), "+f"(c[3])
                    : "r"(a0), "r"(a1), "r"(a2), "r"(a3),
                      "r"(b0), "r"(b1));
            }
        }
        // no trailing __syncthreads: next iteration's top barrier protects reuse
    }

    // ---- epilogue: normalize and write y[b, q, h*64 + d] ----
    float inv1 = 1.f / l1, inv2 = 1.f / l2;
    #pragma unroll
    for (int nt = 0; nt < 8; nt++) {
        int col = h * 64 + nt * 8 + gt * 2;
        if (r1ok) {
            float* dst = y + ((size_t)(b * PN + r1)) * PD + col;
            dst[0] = oacc[nt][0] * inv1;
            dst[1] = oacc[nt][1] * inv1;
        }
        if (r2ok) {
            float* dst = y + ((size_t)(b * PN + r2)) * PD + col;
            dst[0] = oacc[nt][2] * inv2;
            dst[1] = oacc[nt][3] * inv2;
        }
    }
}

// ---------------------------------------------------------------------------
// Launch
// ---------------------------------------------------------------------------
extern "C" void kernel_launch(void* const* d_in, const int* in_sizes, int n_in,
                              void* d_out, int out_size)
{
    (void)in_sizes; (void)n_in; (void)out_size;
    const float* x      = (const float*)d_in[0];
    const float* fc     = (const float*)d_in[1];
    const float* g      = (const float*)d_in[2];
    const float* qkv_w  = (const float*)d_in[3];
    const float* qkv_b  = (const float*)d_in[4];
    const float* out_w  = (const float*)d_in[5];
    const float* out_b  = (const float*)d_in[6];
    const float* gate_w = (const float*)d_in[7];
    const float* gate_b = (const float*)d_in[8];
    const float* Bbias  = (const float*)d_in[9];
    float* out = (float*)d_out;

    float *h, *qkv, *y, *t1;
    cudaGetSymbolAddress((void**)&h,   g_h);
    cudaGetSymbolAddress((void**)&qkv, g_qkv);
    cudaGetSymbolAddress((void**)&y,   g_y);
    cudaGetSymbolAddress((void**)&t1,  g_t1);

    cudaFuncSetAttribute(mma_nt<0>, cudaFuncAttributeMaxDynamicSharedMemorySize, GEMM_SMEM);
    cudaFuncSetAttribute(mma_nt<1>, cudaFuncAttributeMaxDynamicSharedMemorySize, GEMM_SMEM);
    cudaFuncSetAttribute(flash_mma_kernel,
                         cudaFuncAttributeMaxDynamicSharedMemorySize, FLASH_SMEM);

    // 1. zero-centered RMSNorm
    rmsnorm_kernel<<<PM, 256>>>(x, g, h);

    // 2. QKV projection (tf32 tensor cores, async pipeline)
    dim3 g1(3072 / 128, (PM + 127) / 128);
    mma_nt<0><<<g1, 256, GEMM_SMEM>>>(h, qkv_w, qkv_b, qkv, PM, 3072, PD, nullptr, nullptr);

    // 3. RoPE on q,k
    int nrope = PM * PH * (PDh / 2);
    rope_kernel<<<(nrope + 255) / 256, 256>>>(qkv, fc);

    // 4. tensor-core flash attention (double-buffered K/V)
    flash_mma_kernel<<<dim3((PN + 127) / 128, PH, PB), 256, FLASH_SMEM>>>(qkv, Bbias, y);

    // 5. out projection: t1 = y @ out_w^T + out_b
    dim3 g2(PD / 128, (PM + 127) / 128);
    mma_nt<0><<<g2, 256, GEMM_SMEM>>>(y, out_w, out_b, t1, PM, PD, PD, nullptr, nullptr);

    // 6. gated residual: out = x + sigmoid(h @ gate_w^T + gate_b) * t1
    mma_nt<1><<<g2, 256, GEMM_SMEM>>>(h, gate_w, gate_b, out, PM, PD, PD, x, t1);
}